// round 1
// baseline (speedup 1.0000x reference)
#include <cuda_runtime.h>

// Dynamic 5x5 per-pixel convolution + leaky_relu(0.2), replicate padding.
// x:      (N, C, H, W)          f32   -> 8 MB
// kernel: (N, C*25, H, W)       f32   -> 200 MB  (dominant HBM traffic)
// out:    (N, C, H, W)          f32
//
// Strategy: HBM-bound streaming. Each thread computes 4 consecutive w pixels
// (float4). Kernel taps are coalesced LDG.128 (25 per thread, each byte read
// once). x is staged in an 8x264 smem tile per block (replicate padding
// resolved at fill) and consumed via conflict-free LDS.128.

#define W_DIM 256
#define H_DIM 256
#define HW (W_DIM * H_DIM)
#define KS 5
#define PAD 2
#define ROWS_PER_BLOCK 4
#define TILE_ROWS (ROWS_PER_BLOCK + 2 * PAD) // 8
#define SROW 264                             // 256 + 2*PAD padded to 8-float multiple

__global__ __launch_bounds__(256, 8)
void dynconv5x5_kernel(const float* __restrict__ x,
                       const float* __restrict__ kern,
                       float* __restrict__ out)
{
    __shared__ float xs[TILE_ROWS][SROW];

    const int nc  = blockIdx.y;               // fused (n, c) plane index
    const int h0  = blockIdx.x * ROWS_PER_BLOCK;
    const int tid = threadIdx.y * 64 + threadIdx.x;

    // ---- stage x tile (rows h0-2 .. h0+5, cols -2 .. 261, replicate clamp) ----
    const float* xp = x + (size_t)nc * HW;
    #pragma unroll
    for (int idx = tid; idx < TILE_ROWS * SROW; idx += 256) {
        int r = idx / SROW;
        int c = idx - r * SROW;
        int gy = h0 + r - PAD;
        gy = gy < 0 ? 0 : (gy > H_DIM - 1 ? H_DIM - 1 : gy);
        int gx = c - PAD;
        gx = gx < 0 ? 0 : (gx > W_DIM - 1 ? W_DIM - 1 : gx);
        xs[r][c] = __ldg(xp + gy * W_DIM + gx);
    }
    __syncthreads();

    const int tx    = threadIdx.x;   // 0..63 -> 4-pixel group along w
    const int ty    = threadIdx.y;   // 0..3  -> row within block tile
    const int h     = h0 + ty;
    const int wbase = tx * 4;

    // kernel base for this (nc, h, wbase); taps stride by HW
    const float* kbase = kern + (size_t)nc * 25 * HW + (size_t)h * W_DIM + wbase;

    float acc0 = 0.f, acc1 = 0.f, acc2 = 0.f, acc3 = 0.f;

    #pragma unroll
    for (int k1 = 0; k1 < KS; k1++) {
        // 8-float sliding window for this tap row (aligned LDS.128 x2)
        float4 a = *(const float4*)&xs[ty + k1][wbase];
        float4 b = *(const float4*)&xs[ty + k1][wbase + 4];
        float r[8] = {a.x, a.y, a.z, a.w, b.x, b.y, b.z, b.w};
        #pragma unroll
        for (int k2 = 0; k2 < KS; k2++) {
            float4 kv = __ldg((const float4*)(kbase + (size_t)(k1 * KS + k2) * HW));
            acc0 = fmaf(kv.x, r[k2 + 0], acc0);
            acc1 = fmaf(kv.y, r[k2 + 1], acc1);
            acc2 = fmaf(kv.z, r[k2 + 2], acc2);
            acc3 = fmaf(kv.w, r[k2 + 3], acc3);
        }
    }

    // leaky_relu(0.2)
    acc0 = acc0 >= 0.f ? acc0 : 0.2f * acc0;
    acc1 = acc1 >= 0.f ? acc1 : 0.2f * acc1;
    acc2 = acc2 >= 0.f ? acc2 : 0.2f * acc2;
    acc3 = acc3 >= 0.f ? acc3 : 0.2f * acc3;

    float4 o = make_float4(acc0, acc1, acc2, acc3);
    *(float4*)(out + (size_t)nc * HW + (size_t)h * W_DIM + wbase) = o;
}

extern "C" void kernel_launch(void* const* d_in, const int* in_sizes, int n_in,
                              void* d_out, int out_size)
{
    const float* x    = (const float*)d_in[0];
    const float* kern = (const float*)d_in[1];
    float* out        = (float*)d_out;

    const int NC = in_sizes[0] / HW;          // 32 for (4,8,256,256)

    dim3 block(64, 4);
    dim3 grid(H_DIM / ROWS_PER_BLOCK, NC);    // (64, 32)
    dynconv5x5_kernel<<<grid, block>>>(x, kern, out);
}

// round 2
// speedup vs baseline: 1.1759x; 1.1759x over previous
#include <cuda_runtime.h>

// Dynamic 5x5 per-pixel convolution + leaky_relu(0.2), replicate padding.
// x:      (N, C, H, W)    f32  -> 8 MB   (staged in smem, 25x reuse)
// kernel: (N, C*25, H, W) f32  -> 200 MB (dominant HBM stream, read once)
// out:    (N, C, H, W)    f32  -> 8 MB
//
// R1 change: 64-reg budget + double-buffered tap-row loads (10 LDG.128 in
// flight) to raise MLP and saturate DRAM; __ldcs on the streamed kernel.

#define W_DIM 256
#define H_DIM 256
#define HW (W_DIM * H_DIM)
#define KS 5
#define PAD 2
#define ROWS_PER_BLOCK 4
#define TILE_ROWS (ROWS_PER_BLOCK + 2 * PAD) // 8
#define SROW 264                             // 256 + 2*PAD, padded for alignment

__global__ __launch_bounds__(256, 4)
void dynconv5x5_kernel(const float* __restrict__ x,
                       const float* __restrict__ kern,
                       float* __restrict__ out)
{
    __shared__ float xs[TILE_ROWS][SROW];

    const int nc  = blockIdx.y;               // fused (n, c) plane index
    const int h0  = blockIdx.x * ROWS_PER_BLOCK;
    const int tid = threadIdx.y * 64 + threadIdx.x;

    // ---- stage x tile (rows h0-2 .. h0+5, cols -2 .. 261, replicate clamp) ----
    const float* xp = x + (size_t)nc * HW;
    #pragma unroll
    for (int idx = tid; idx < TILE_ROWS * SROW; idx += 256) {
        int r = idx / SROW;
        int c = idx - r * SROW;
        int gy = h0 + r - PAD;
        gy = gy < 0 ? 0 : (gy > H_DIM - 1 ? H_DIM - 1 : gy);
        int gx = c - PAD;
        gx = gx < 0 ? 0 : (gx > W_DIM - 1 ? W_DIM - 1 : gx);
        xs[r][c] = __ldg(xp + gy * W_DIM + gx);
    }
    __syncthreads();

    const int tx    = threadIdx.x;   // 0..63 -> 4-pixel group along w
    const int ty    = threadIdx.y;   // 0..3  -> row within block tile
    const int h     = h0 + ty;
    const int wbase = tx * 4;

    // kernel base for this (nc, h, wbase); taps stride by HW
    const float* kbase = kern + (size_t)nc * 25 * HW + (size_t)h * W_DIM + wbase;

    float acc0 = 0.f, acc1 = 0.f, acc2 = 0.f, acc3 = 0.f;

    // Double-buffered tap rows: issue next row's 5 LDG.128 before consuming
    // the current row -> up to 10 independent loads in flight per thread.
    float4 kv[2][KS];
    #pragma unroll
    for (int k2 = 0; k2 < KS; k2++)
        kv[0][k2] = __ldcs((const float4*)(kbase + (size_t)k2 * HW));

    #pragma unroll
    for (int k1 = 0; k1 < KS; k1++) {
        const int cur = k1 & 1;
        if (k1 < KS - 1) {
            #pragma unroll
            for (int k2 = 0; k2 < KS; k2++)
                kv[cur ^ 1][k2] =
                    __ldcs((const float4*)(kbase + (size_t)((k1 + 1) * KS + k2) * HW));
        }

        // 8-float sliding window for this tap row (aligned LDS.128 x2)
        float4 a = *(const float4*)&xs[ty + k1][wbase];
        float4 b = *(const float4*)&xs[ty + k1][wbase + 4];
        float r[8] = {a.x, a.y, a.z, a.w, b.x, b.y, b.z, b.w};

        #pragma unroll
        for (int k2 = 0; k2 < KS; k2++) {
            float4 c4 = kv[cur][k2];
            acc0 = fmaf(c4.x, r[k2 + 0], acc0);
            acc1 = fmaf(c4.y, r[k2 + 1], acc1);
            acc2 = fmaf(c4.z, r[k2 + 2], acc2);
            acc3 = fmaf(c4.w, r[k2 + 3], acc3);
        }
    }

    // leaky_relu(0.2)
    acc0 = acc0 >= 0.f ? acc0 : 0.2f * acc0;
    acc1 = acc1 >= 0.f ? acc1 : 0.2f * acc1;
    acc2 = acc2 >= 0.f ? acc2 : 0.2f * acc2;
    acc3 = acc3 >= 0.f ? acc3 : 0.2f * acc3;

    float4 o = make_float4(acc0, acc1, acc2, acc3);
    *(float4*)(out + (size_t)nc * HW + (size_t)h * W_DIM + wbase) = o;
}

extern "C" void kernel_launch(void* const* d_in, const int* in_sizes, int n_in,
                              void* d_out, int out_size)
{
    const float* x    = (const float*)d_in[0];
    const float* kern = (const float*)d_in[1];
    float* out        = (float*)d_out;

    const int NC = in_sizes[0] / HW;          // 32 for (4,8,256,256)

    dim3 block(64, 4);
    dim3 grid(H_DIM / ROWS_PER_BLOCK, NC);    // (64, 32)
    dynconv5x5_kernel<<<grid, block>>>(x, kern, out);
}